// round 10
// baseline (speedup 1.0000x reference)
#include <cuda_runtime.h>
#include <cstdint>

// Problem shape (fixed for this dataset):
//   pool: f32  [16, 128, 128, 64]  -> 16,777,216 elements
//   ind : i32  same shape, values in [0, 4,194,304)
//   out : f32  [16, 256, 256, 64]  -> 67,108,864 elements (256 MB)
// Per-batch flat scatter-ADD (duplicates sum).
//
// Wavefront ledger (R3-R9 measured): L1tex adds ~2 cyc per wavefront for
// atomics AND stores alike; atomics = 16.7M wf = ~131 us wall. Zeroing via
// per-lane stores adds ~12 us no matter how it's scheduled. This round
// DELETES the zero wavefronts: each zero block fills a 16 KB SMEM zero
// buffer ONCE, then issues 32 TMA bulk stores (cp.async.bulk -> UTMASTG)
// from it -> 512 KB zeroed per block at 1/32 the per-lane cost; the writes
// ride the TMA/LTS path concurrently with the atomic grind.
// Pipeline: 8 x 2-batch chunks (L2 live set 32 cur + 32 next + 16 in = 80 MB
// < 126 MB). Kernel k: 64 zero blocks (chunk k+1) + 2048 scatter blocks
// (chunk k). Head: one 32 MB memset for chunk 0.

static constexpr int  PB_IN_V4_LOG2     = 18;   // per-batch input elems/4 = 2^18
static constexpr int  OUT_FLAT_LOG2     = 22;   // per-batch output elems = 2^22
static constexpr int  BATCHES           = 16;
static constexpr int  BATCHES_PER_CHUNK = 2;
static constexpr int  NCHUNKS           = BATCHES / BATCHES_PER_CHUNK;   // 8

static constexpr int  CHUNK_IN_V4     = BATCHES_PER_CHUNK << PB_IN_V4_LOG2;        // 524,288
static constexpr long CHUNK_OUT_ELEM  = (long)BATCHES_PER_CHUNK << OUT_FLAT_LOG2;  // 8,388,608
static constexpr long CHUNK_OUT_BYTES = CHUNK_OUT_ELEM * 4;                        // 32 MB

static constexpr int  THREADS        = 256;
static constexpr int  SCATTER_BLOCKS = CHUNK_IN_V4 / THREADS;   // 2048

static constexpr int  ZBYTES   = 16384;                         // SMEM zero buffer
static constexpr int  ZBUF_F4  = ZBYTES / 16;                   // 1024 float4
static constexpr int  TMA_STORES_PER_BLOCK = 32;                // 512 KB per block
static constexpr int  NZB = (int)(CHUNK_OUT_BYTES / ((long)ZBYTES * TMA_STORES_PER_BLOCK)); // 64

// ---------------------------------------------------------------------------
// Fused kernel. Blocks [0, nzb): zero 512 KB of chunk k+1 each via one SMEM
// fill + 32 TMA bulk stores. Blocks [nzb, nzb+2048): scatter chunk k
// (R3-proven 4-atomic body).
// ---------------------------------------------------------------------------
__global__ void __launch_bounds__(THREADS)
unpool_fused_tma(const float4* __restrict__ pool4,
                 const int4*   __restrict__ ind4,
                 float*        __restrict__ out,
                 char*         __restrict__ zero_base,
                 int            nzb) {
    const int bid = blockIdx.x;

    if (bid < nzb) {
        // ---- zero 512 KB of chunk k+1 via TMA bulk stores ----
        __shared__ __align__(128) float4 zbuf[ZBUF_F4];   // 16 KB of zeros

        const float4 z = make_float4(0.f, 0.f, 0.f, 0.f);
        #pragma unroll
        for (int j = 0; j < ZBUF_F4 / THREADS; ++j) {
            zbuf[threadIdx.x + j * THREADS] = z;
        }
        __syncthreads();
        // Make generic-proxy SMEM writes visible to the async (TMA) proxy.
        asm volatile("fence.proxy.async.shared::cta;" ::: "memory");

        if (threadIdx.x == 0) {
            uint32_t saddr;
            asm("{ .reg .u64 tmp; cvta.to.shared.u64 tmp, %1; cvt.u32.u64 %0, tmp; }"
                : "=r"(saddr) : "l"(zbuf));
            char* gdst = zero_base + (long)bid * (long)ZBYTES * TMA_STORES_PER_BLOCK;
            #pragma unroll
            for (int s = 0; s < TMA_STORES_PER_BLOCK; ++s) {
                asm volatile(
                    "cp.async.bulk.global.shared::cta.bulk_group [%0], [%1], %2;"
                    :: "l"(gdst + (long)s * ZBYTES), "r"(saddr), "r"((uint32_t)ZBYTES)
                    : "memory");
            }
            asm volatile("cp.async.bulk.commit_group;" ::: "memory");
            // Bulk stores must be drained before thread exit; kernel completion
            // then orders them before the next chunk's atomics (stream order).
            asm volatile("cp.async.bulk.wait_group 0;" ::: "memory");
        }
        return;
    }

    // ---- scatter chunk k ----
    const int t = (bid - nzb) * THREADS + threadIdx.x;

    // Streaming loads (evict-first): keep L2 for the output slices.
    float4 p = __ldcs(pool4 + t);
    int4   i = __ldcs(ind4 + t);

    long base = (long)(t >> PB_IN_V4_LOG2) << OUT_FLAT_LOG2;

    atomicAdd(out + base + (long)(unsigned)i.x, p.x);
    atomicAdd(out + base + (long)(unsigned)i.y, p.y);
    atomicAdd(out + base + (long)(unsigned)i.z, p.z);
    atomicAdd(out + base + (long)(unsigned)i.w, p.w);
}

// ---------------------------------------------------------------------------
extern "C" void kernel_launch(void* const* d_in, const int* in_sizes, int n_in,
                              void* d_out, int out_size) {
    const float4* pool4 = (const float4*)d_in[0];
    const int4*   ind4  = (const int4*)d_in[1];
    float*        out   = (float*)d_out;

    // Head: zero chunk 0 (32 MB, ~2 us, L2-absorbed).
    cudaMemsetAsync(out, 0, CHUNK_OUT_BYTES, 0);

    for (int c = 0; c < NCHUNKS; ++c) {
        float* out_cur = out + (long)c * CHUNK_OUT_ELEM;
        char*  zero_nx = (c + 1 < NCHUNKS)
                       ? (char*)(out + (long)(c + 1) * CHUNK_OUT_ELEM)
                       : nullptr;
        int    nzb     = (zero_nx != nullptr) ? NZB : 0;

        unpool_fused_tma<<<SCATTER_BLOCKS + nzb, THREADS>>>(
            pool4 + (long)c * CHUNK_IN_V4,
            ind4  + (long)c * CHUNK_IN_V4,
            out_cur,
            zero_nx,
            nzb);
    }
}

// round 11
// speedup vs baseline: 1.2333x; 1.2333x over previous
#include <cuda_runtime.h>
#include <cstdint>

// Problem shape (fixed for this dataset):
//   pool: f32  [16, 128, 128, 64]  -> 16,777,216 elements
//   ind : i32  same shape, values in [0, 4,194,304)
//   out : f32  [16, 256, 256, 64]  -> 67,108,864 elements (256 MB)
// Per-batch flat scatter-ADD (duplicates sum).
//
// Final model (R3-R10, six structural variants measured):
//  - Divergent-atomic scatter floor ~2.1 cyc/atomic/SM => ~131-136 us total,
//    invariant to occupancy / ILP / grid shape / instruction interleave.
//  - Zero-store work is conserved across every overlap scheme (STG spread,
//    STG dedicated blocks, TMA bulk): all cost MORE than serialized
//    cudaMemsetAsync, which hits a driver zero-fill fast path (~12 us/256MB).
//  - Output slice must stay L2-resident during its scatter (R7: eviction
//    costs ~40% on the chunk).
// => R3 structure (memset chunk; scatter chunk) x 4 is the winner.
// This round adds the one remaining lever: __ldcs (evict-first) on the
// 32 MB/chunk of streamed inputs so they don't evict the 64 MB output slice.

static constexpr int  PB_IN_V4_LOG2     = 18;   // per-batch input elems/4 = 2^18
static constexpr int  OUT_FLAT_LOG2     = 22;   // per-batch output elems = 2^22
static constexpr int  BATCHES           = 16;
static constexpr int  BATCHES_PER_CHUNK = 4;
static constexpr int  NCHUNKS           = BATCHES / BATCHES_PER_CHUNK;   // 4

static constexpr int  CHUNK_IN_V4    = BATCHES_PER_CHUNK << PB_IN_V4_LOG2;        // 1,048,576
static constexpr long CHUNK_OUT_ELEM = (long)BATCHES_PER_CHUNK << OUT_FLAT_LOG2;  // 16,777,216

static constexpr int  THREADS = 256;

// ---------------------------------------------------------------------------
// Scatter-add for one chunk of BATCHES_PER_CHUNK batches (R3-proven body).
// Inputs loaded evict-first so the streamed 32 MB doesn't displace the
// L2-resident output slice the atomics are hitting.
// ---------------------------------------------------------------------------
__global__ void __launch_bounds__(THREADS)
unpool_scatter_chunk(const float4* __restrict__ pool4,
                     const int4*   __restrict__ ind4,
                     float*        __restrict__ out,
                     int n4) {
    int t = blockIdx.x * blockDim.x + threadIdx.x;
    if (t >= n4) return;

    // Front-batch loads (independent -> MLP), evict-first policy.
    float4 p = __ldcs(pool4 + t);
    int4   i = __ldcs(ind4 + t);

    int  b    = t >> PB_IN_V4_LOG2;          // batch within chunk (0..3)
    long base = (long)b << OUT_FLAT_LOG2;    // local batch output base

    atomicAdd(out + base + (long)(unsigned)i.x, p.x);
    atomicAdd(out + base + (long)(unsigned)i.y, p.y);
    atomicAdd(out + base + (long)(unsigned)i.z, p.z);
    atomicAdd(out + base + (long)(unsigned)i.w, p.w);
}

// ---------------------------------------------------------------------------
extern "C" void kernel_launch(void* const* d_in, const int* in_sizes, int n_in,
                              void* d_out, int out_size) {
    const float4* pool4 = (const float4*)d_in[0];
    const int4*   ind4  = (const int4*)d_in[1];
    float*        out   = (float*)d_out;

    const int blocks = (CHUNK_IN_V4 + THREADS - 1) / THREADS;

    for (int c = 0; c < NCHUNKS; ++c) {
        float* out_chunk = out + (long)c * CHUNK_OUT_ELEM;

        // Zero this chunk's output slice (driver zero-fill fast path;
        // lines stay L2-resident for the scatter).
        cudaMemsetAsync(out_chunk, 0, CHUNK_OUT_ELEM * sizeof(float), 0);

        // Scatter-add this chunk's 4 batches while the slice is hot in L2.
        unpool_scatter_chunk<<<blocks, THREADS>>>(
            pool4 + (long)c * CHUNK_IN_V4,
            ind4  + (long)c * CHUNK_IN_V4,
            out_chunk,
            CHUNK_IN_V4);
    }
}